// round 16
// baseline (speedup 1.0000x reference)
#include <cuda_runtime.h>
#include <cuda_fp16.h>
#include <math.h>
#include <stdint.h>

#define B_   2
#define C_   128
#define H_   96
#define W_   320
#define HW_  30720
#define CQ_  32
#define D_   32
#define NPIX_ (B_*HW_)
#define XEL_  (B_*C_*HW_)
#define NCEL_ (B_*D_*HW_)
#define PH_  98
#define PW_  322

typedef unsigned long long u64;

#define FMA2(d,a,b,c) asm("fma.rn.f32x2 %0, %1, %2, %3;" : "=l"(d) : "l"(a), "l"(b), "l"(c))
#define PACK2(d,lo,hi) asm("mov.b64 %0, {%1, %2};" : "=l"(d) : "r"(__float_as_uint(lo)), "r"(__float_as_uint(hi)))
#define UNPK2(lo,hi,s) do { unsigned _a,_b; asm("mov.b64 {%0, %1}, %2;" : "=r"(_a), "=r"(_b) : "l"(s)); lo=__uint_as_float(_a); hi=__uint_as_float(_b); } while(0)

// ---------------- scratch ----------------
__device__ float  g_sim[NCEL_];
__device__ __align__(16) __half g_phi[(size_t)B_*PH_*PW_*C_];
__device__ __align__(16) unsigned short g_wH[18][8192];
__device__ float  g_faproj[40];
__device__ float  g_fw[C_];
__device__ float  g_partf[4*480*2];
__device__ float  g_stats[8];
__device__ float  g_cpart[480*128];
__device__ float  g_yscale[B_*C_];

// ---------------- low-level helpers ----------------
__device__ __forceinline__ uint32_t smem_u32(const void* p) {
    uint32_t a;
    asm("{ .reg .u64 t; cvta.to.shared.u64 t, %1; cvt.u32.u64 %0, t; }" : "=r"(a) : "l"(p));
    return a;
}
#define CP16(sm, gp) asm volatile("cp.async.cg.shared.global [%0], [%1], 16;" :: "r"(sm), "l"(gp) : "memory")
#define CP_COMMIT()  asm volatile("cp.async.commit_group;" ::: "memory")
#define CP_WAIT(n)   asm volatile("cp.async.wait_group %0;" :: "n"(n) : "memory")

__device__ __forceinline__ void ldsm_x4(uint32_t* r, uint32_t addr) {
    asm volatile("ldmatrix.sync.aligned.m8n8.x4.shared.b16 {%0,%1,%2,%3}, [%4];"
        : "=r"(r[0]), "=r"(r[1]), "=r"(r[2]), "=r"(r[3]) : "r"(addr));
}
__device__ __forceinline__ void mma16816h(float* d, const uint32_t* a, uint32_t b0, uint32_t b1) {
    asm volatile("mma.sync.aligned.m16n8k16.row.col.f32.f16.f16.f32 "
        "{%0,%1,%2,%3}, {%4,%5,%6,%7}, {%8,%9}, {%0,%1,%2,%3};"
        : "+f"(d[0]), "+f"(d[1]), "+f"(d[2]), "+f"(d[3])
        : "r"(a[0]), "r"(a[1]), "r"(a[2]), "r"(a[3]), "r"(b0), "r"(b1));
}

// ---------------- combined weight preprocessing ----------------
__global__ void __launch_bounds__(256) k_prepall(const float* __restrict__ fa_w,
                                                 const float* __restrict__ ce_w,
                                                 const float* __restrict__ ce_b,
                                                 const float* __restrict__ nt_w,
                                                 const float* __restrict__ nt_b,
                                                 const float* __restrict__ rc_w) {
    int blk = blockIdx.x;
    if (blk == 0) {
        int t = threadIdx.x;
        if (t < 32) {
            float s = 0.f;
            for (int o = 0; o < C_; o++) s += fa_w[C_ + o] * ce_w[o * D_ + t];
            g_faproj[t] = s;
        } else if (t == 32) {
            float s = 0.f;
            for (int o = 0; o < C_; o++) s += fa_w[C_ + o] * ce_b[o];
            g_faproj[32] = s;
        } else if (t == 33) {
            float s = 0.f;
            for (int c = 0; c < C_; c++) s += fa_w[c] * nt_b[c];
            g_faproj[33] = s;
        } else if (t == 34) {
            float s = 0.f;
            for (int c = 0; c < C_; c++) s += fa_w[c] * nt_w[c];
            g_faproj[34] = s;
        } else if (t >= 64 && t < 64 + C_) {
            int c = t - 64;
            g_fw[c] = fa_w[c] * nt_w[c];
        }
    } else {
        int it = blk - 1;
        int tap = it % 9, chunk = it / 9;
        for (int idx = threadIdx.x; idx < 8192; idx += 256) {
            int oc = idx >> 6, icl = idx & 63;
            int ic = chunk * 64 + icl;
            float w = rc_w[(oc * C_ + ic) * 9 + tap];
            int pos = oc * 64 + (((icl >> 3) ^ (oc & 7)) << 3) + (icl & 7);
            g_wH[it][pos] = __half_as_ushort(__float2half_rn(w));
        }
    }
}

// ---------------- fused q/k projection + warp + cosine sim + t-stats (640 thr, 2/pixel) ----------------
#define SQ_KSH 0
#define SQ_WQ  40960
#define SQ_WK  57344
#define SQ_BQ  73728
#define SQ_BK  73856
#define SQ_R1  73984
#define SQ_R2  74064
#define SIMQK_SMEM 74144

__global__ void __launch_bounds__(2 * W_) k_simqk(const float* __restrict__ t_feat,
                                                  const float* __restrict__ s_feat,
                                                  const float* __restrict__ q_w,
                                                  const float* __restrict__ q_b,
                                                  const float* __restrict__ k_w,
                                                  const float* __restrict__ k_b,
                                                  const float* __restrict__ disp,
                                                  const float* __restrict__ directs) {
    extern __shared__ __align__(16) char sm[];
    float* ksh = reinterpret_cast<float*>(sm + SQ_KSH);
    u64*   wq  = reinterpret_cast<u64*>(sm + SQ_WQ);
    u64*   wk  = reinterpret_cast<u64*>(sm + SQ_WK);
    float* bq  = reinterpret_cast<float*>(sm + SQ_BQ);
    float* bk  = reinterpret_cast<float*>(sm + SQ_BK);
    float* r1  = reinterpret_cast<float*>(sm + SQ_R1);
    float* r2  = reinterpret_cast<float*>(sm + SQ_R2);

    int h = blockIdx.x, b = blockIdx.y;
    int tid = threadIdx.x;
    int wl = tid >> 1, y = tid & 1;     // 2 adjacent lanes per pixel
    int lane = tid & 31, wrp = tid >> 5;

    for (int i = tid; i < C_ * 16; i += 2 * W_) {
        int c = i >> 4, op = i & 15;
        u64 t;
        PACK2(t, q_w[(2 * op) * C_ + c], q_w[(2 * op + 1) * C_ + c]);
        wq[i] = t;
        PACK2(t, k_w[(2 * op) * C_ + c], k_w[(2 * op + 1) * C_ + c]);
        wk[i] = t;
    }
    if (tid < CQ_) { bq[tid] = q_b[tid]; bk[tid] = k_b[tid]; }
    __syncthreads();

    // ---- k projection: this thread computes op-pairs [y*8, y*8+8) ----
    {
        const float* fp = s_feat + (size_t)b * C_ * HW_ + h * W_ + wl;
        u64 acc[8];
#pragma unroll
        for (int o = 0; o < 8; o++) acc[o] = 0ULL;
#pragma unroll 4
        for (int c = 0; c < C_; c++) {
            float v = fp[(size_t)c * HW_];
            u64 v2; PACK2(v2, v, v);
#pragma unroll
            for (int o = 0; o < 8; o++) FMA2(acc[o], wk[c * 16 + y * 8 + o], v2, acc[o]);
        }
#pragma unroll
        for (int o = 0; o < 8; o++) {
            int op = y * 8 + o;
            float lo, hi; UNPK2(lo, hi, acc[o]);
            ksh[(2 * op) * W_ + wl]     = lo + bk[2 * op];
            ksh[(2 * op + 1) * W_ + wl] = hi + bk[2 * op + 1];
        }
    }

    // ---- q projection (own 16 channels) + t-stats (y==0 only) ----
    float qv[16];
    float s1 = 0.f, s2 = 0.f;
    float n2own = 0.f;
    {
        const float* tp = t_feat + (size_t)b * C_ * HW_ + h * W_ + wl;
        u64 acc[8];
#pragma unroll
        for (int o = 0; o < 8; o++) acc[o] = 0ULL;
#pragma unroll 4
        for (int c = 0; c < C_; c++) {
            float v = tp[(size_t)c * HW_];
            if (y == 0) { s1 += v; s2 += v * v; }
            u64 v2; PACK2(v2, v, v);
#pragma unroll
            for (int o = 0; o < 8; o++) FMA2(acc[o], wq[c * 16 + y * 8 + o], v2, acc[o]);
        }
#pragma unroll
        for (int o = 0; o < 8; o++) {
            int op = y * 8 + o;
            float lo, hi; UNPK2(lo, hi, acc[o]);
            lo += bq[2 * op]; hi += bq[2 * op + 1];
            qv[2 * o] = lo; qv[2 * o + 1] = hi;
            n2own += lo * lo + hi * hi;
        }
    }
    // join norm + exchange q halves with partner lane
    float n2 = n2own + __shfl_xor_sync(0xFFFFFFFFu, n2own, 1);
    float invq = 1.f / fmaxf(sqrtf(n2), 1e-12f);
    float qr[32];
#pragma unroll
    for (int j = 0; j < 16; j++) {
        float pv = __shfl_xor_sync(0xFFFFFFFFu, qv[j], 1);
        qr[y * 16 + j]       = qv[j] * invq;
        qr[(1 - y) * 16 + j] = pv * invq;
    }
    __syncthreads();   // ksh complete

    // ---- warp + cosine sim: 16 d's per thread ----
    float dir = directs[b];
    float* sp = g_sim + (size_t)b * D_ * HW_ + h * W_ + wl;
#pragma unroll 2
    for (int j = 0; j < 16; j++) {
        int d = y * 16 + j;
        float pos = (float)wl + disp[d] * dir * (float)(W_ - 1);
        pos = fminf(fmaxf(pos, 0.f), (float)(W_ - 1));
        int x0 = (int)floorf(pos);
        x0 = min(max(x0, 0), W_ - 1);
        int x1 = min(x0 + 1, W_ - 1);
        float t = pos - (float)x0;
        float dot = 0.f, kn2 = 0.f;
#pragma unroll
        for (int c = 0; c < CQ_; c++) {
            float a = ksh[c * W_ + x0];
            float g = a + t * (ksh[c * W_ + x1] - a);
            dot += qr[c] * g;
            kn2 += g * g;
        }
        sp[(size_t)d * HW_] = dot / fmaxf(sqrtf(kn2), 1e-12f);
    }

    // ---- t-stats block reduce (y==0 contributed; odd lanes hold 0) ----
#pragma unroll
    for (int o = 16; o > 0; o >>= 1) {
        s1 += __shfl_xor_sync(0xFFFFFFFFu, s1, o);
        s2 += __shfl_xor_sync(0xFFFFFFFFu, s2, o);
    }
    if (lane == 0) { r1[wrp] = s1; r2[wrp] = s2; }
    __syncthreads();
    if (tid == 0) {
        float t1 = 0.f, t2 = 0.f;
#pragma unroll
        for (int i = 0; i < 20; i++) { t1 += r1[i]; t2 += r2[i]; }
        g_partf[((0 * 2 + b) * 480 + h) * 2 + 0] = t1;
        g_partf[((0 * 2 + b) * 480 + h) * 2 + 1] = t2;
    }
}

// ---------------- fused cost filter + softmax + c-stats ----------------
template<int Y>
__device__ __forceinline__ void cost_half(float* cl, const float* __restrict__ base,
                                          const float* __restrict__ wsh,
                                          int h, int w, int lane) {
#pragma unroll
    for (int j = 0; j < 17; j++) {
        const int dd = Y ? (15 + j) : j;
        const int t  = Y ? (j - 1) : j;
        float s0 = 0.f, s1 = 0.f, s2 = 0.f;
#pragma unroll
        for (int r = 0; r < 3; r++) {
            int hh = h + r - 1;
            bool ok = (hh >= 0) && (hh < H_);
            const float* row = base + ((size_t)dd * H_ + hh) * W_;
            float v = ok ? row[w] : 0.f;
            float vm = __shfl_up_sync(0xFFFFFFFFu, v, 1);
            float vp = __shfl_down_sync(0xFFFFFFFFu, v, 1);
            if (lane == 0)  vm = (ok && w > 0)      ? row[w - 1] : 0.f;
            if (lane == 31) vp = (ok && w < W_ - 1) ? row[w + 1] : 0.f;
            s0 += wsh[r * 3 + 0] * vm + wsh[r * 3 + 1] * v + wsh[r * 3 + 2] * vp;
            s1 += wsh[9 + r * 3 + 0] * vm + wsh[9 + r * 3 + 1] * v + wsh[9 + r * 3 + 2] * vp;
            s2 += wsh[18 + r * 3 + 0] * vm + wsh[18 + r * 3 + 1] * v + wsh[18 + r * 3 + 2] * vp;
        }
        if (t + 1 >= 0 && t + 1 < 16 && dd + 1 < D_) cl[t + 1] += s0;
        if (t >= 0 && t < 16)                        cl[t]     += s1;
        if (t - 1 >= 0 && t - 1 < 16)                cl[t - 1] += s2;
    }
}

__global__ void __launch_bounds__(128) k_costsoft(const float* __restrict__ cf_w,
                                                  float* __restrict__ out) {
    __shared__ float wsh[27];
    __shared__ float mx[2][64], sms[2][64];
    __shared__ float r1s[4], r2s[4];
    int h = blockIdx.x / 5, tile = blockIdx.x % 5, b = blockIdx.y;
    int wl = threadIdx.x, y = threadIdx.y;
    int w = tile * 64 + wl;
    int tid = y * 64 + wl;
    int lane = wl & 31;
    if (tid < 27) wsh[tid] = cf_w[tid];
    __syncthreads();

    const float* base = g_sim + (size_t)b * D_ * HW_;
    float cl[16];
#pragma unroll
    for (int j = 0; j < 16; j++) cl[j] = 0.f;
    if (y == 0) cost_half<0>(cl, base, wsh, h, w, lane);
    else        cost_half<1>(cl, base, wsh, h, w, lane);

    float m = -1e30f;
#pragma unroll
    for (int j = 0; j < 16; j++) m = fmaxf(m, cl[j]);
    mx[y][wl] = m;
    __syncthreads();
    m = fmaxf(mx[0][wl], mx[1][wl]);
    float sum = 0.f;
#pragma unroll
    for (int j = 0; j < 16; j++) { cl[j] = expf(cl[j] - m); sum += cl[j]; }
    sms[y][wl] = sum;
    __syncthreads();
    float invs = 1.f / (sms[0][wl] + sms[1][wl]);

    int d0 = y * 16;
    float* op = out + XEL_ + (size_t)b * D_ * HW_ + (size_t)d0 * HW_ + h * W_ + w;
    float ss1 = 0.f, ss2 = 0.f;
#pragma unroll
    for (int j = 0; j < 16; j++) {
        float v = cl[j] * invs;
        op[(size_t)j * HW_] = v;
        ss1 += v; ss2 += v * v;
    }
#pragma unroll
    for (int o = 16; o > 0; o >>= 1) {
        ss1 += __shfl_xor_sync(0xFFFFFFFFu, ss1, o);
        ss2 += __shfl_xor_sync(0xFFFFFFFFu, ss2, o);
    }
    if (lane == 0) { r1s[tid >> 5] = ss1; r2s[tid >> 5] = ss2; }
    __syncthreads();
    if (tid == 0) {
        g_partf[((1 * 2 + b) * 480 + h * 5 + tile) * 2 + 0] = r1s[0] + r1s[1] + r1s[2] + r1s[3];
        g_partf[((1 * 2 + b) * 480 + h * 5 + tile) * 2 + 1] = r2s[0] + r2s[1] + r2s[2] + r2s[3];
    }
}

// ---------------- stats finals ----------------
__global__ void __launch_bounds__(512) k_statsfinal() {
    __shared__ double sh1[512], sh2[512];
    int which = blockIdx.x >> 1, b = blockIdx.x & 1;
    int n = which ? 480 : 96;
    int t = threadIdx.x;
    double s1 = 0.0, s2 = 0.0;
    if (t < n) {
        s1 = (double)g_partf[((which * 2 + b) * 480 + t) * 2 + 0];
        s2 = (double)g_partf[((which * 2 + b) * 480 + t) * 2 + 1];
    }
    sh1[t] = s1; sh2[t] = s2;
    __syncthreads();
    for (int s = 256; s > 0; s >>= 1) {
        if (t < s) { sh1[t] += sh1[t + s]; sh2[t] += sh2[t + s]; }
        __syncthreads();
    }
    if (t == 0) {
        double N = which ? (double)(D_ * HW_) : (double)(C_ * HW_);
        double mu  = sh1[0] / N;
        double var = sh2[0] / N - mu * mu;
        g_stats[which * 4 + b * 2 + 0] = (float)mu;
        g_stats[which * 4 + b * 2 + 1] = (float)(1.0 / sqrt(var + 1e-5));
    }
}

// ---------------- fuse: GEMM-tiled cost-embed + gating ----------------
#define FS_CN    0
#define FS_CEP   17408
#define FS_FUSED 0
#define FS_ALPHA 34816
#define FS_NCW   35328
#define FS_NCB   35456
#define FS_PROJ  35584
#define FS_FW    35744
#define FS_NTW   36256
#define FS_NTB   36768
#define FS_CEB   37280
#define FUSE_SMEM 37888

__global__ void __launch_bounds__(256) k_fuse(const float* __restrict__ out_base,
                                              const float* __restrict__ t_feat,
                                              const float* __restrict__ nt_w,
                                              const float* __restrict__ nt_b,
                                              const float* __restrict__ nc_w,
                                              const float* __restrict__ nc_b,
                                              const float* __restrict__ ce_w,
                                              const float* __restrict__ ce_b,
                                              const float* __restrict__ fa_b) {
    extern __shared__ __align__(16) char sm[];
    float* cn_s   = reinterpret_cast<float*>(sm + FS_CN);
    float* cep_s  = reinterpret_cast<float*>(sm + FS_CEP);
    __half* fu_s  = reinterpret_cast<__half*>(sm + FS_FUSED);
    float* alp_s  = reinterpret_cast<float*>(sm + FS_ALPHA);
    float* ncw_s  = reinterpret_cast<float*>(sm + FS_NCW);
    float* ncb_s  = reinterpret_cast<float*>(sm + FS_NCB);
    float* proj_s = reinterpret_cast<float*>(sm + FS_PROJ);
    float* fw_s   = reinterpret_cast<float*>(sm + FS_FW);
    float* ntw_s  = reinterpret_cast<float*>(sm + FS_NTW);
    float* ntb_s  = reinterpret_cast<float*>(sm + FS_NTB);
    float* ceb_s  = reinterpret_cast<float*>(sm + FS_CEB);

    int tid = threadIdx.x;
    {
        const float4* cw4 = reinterpret_cast<const float4*>(ce_w);
#pragma unroll
        for (int j = 0; j < 4; j++) {
            int i4 = tid + j * 256;
            float4 v = cw4[i4];
            int base = i4 * 4;
            int oc = base >> 5, d = base & 31;
            cep_s[(d + 0) * 128 + oc] = v.x;
            cep_s[(d + 1) * 128 + oc] = v.y;
            cep_s[(d + 2) * 128 + oc] = v.z;
            cep_s[(d + 3) * 128 + oc] = v.w;
        }
    }
    if (tid < C_) {
        ntw_s[tid] = nt_w[tid];
        ntb_s[tid] = nt_b[tid];
        ceb_s[tid] = ce_b[tid];
        fw_s[tid]  = g_fw[tid];
    }
    if (tid < D_) { ncw_s[tid] = nc_w[tid]; ncb_s[tid] = nc_b[tid]; }
    if (tid >= 128 && tid < 168) proj_s[tid - 128] = g_faproj[tid - 128];
    __syncthreads();

    int blk = blockIdx.x;
    int b = (blk >= 240) ? 1 : 0;
    int pix0 = (blk * 128) % HW_;
    float mu_t = g_stats[b * 2 + 0], inv_t = g_stats[b * 2 + 1];
    float mu_c = g_stats[4 + b * 2 + 0], inv_c = g_stats[4 + b * 2 + 1];

    {
        int pixl = tid >> 1, half = tid & 1;
        int pixg = pix0 + pixl;
        const float* ncp = out_base + XEL_ + (size_t)b * D_ * HW_ + pixg;
        float alin = half ? 0.f
                          : (fa_b[0] + proj_s[32] + proj_s[33] - inv_t * mu_t * proj_s[34]);
#pragma unroll
        for (int j = 0; j < 16; j++) {
            int d = half * 16 + j;
            float v = (ncp[(size_t)d * HW_] - mu_c) * inv_c * ncw_s[d] + ncb_s[d];
            cn_s[d * 136 + pixl] = v;
            alin += proj_s[d] * v;
        }
        const float* tp = t_feat + (size_t)b * C_ * HW_ + pixg;
        float dotft = 0.f;
#pragma unroll 4
        for (int cc = 0; cc < 64; cc++) {
            int c = half * 64 + cc;
            dotft += fw_s[c] * tp[(size_t)c * HW_];
        }
        alin += inv_t * dotft;
        alin += __shfl_xor_sync(0xFFFFFFFFu, alin, 1);
        if (half == 0) alp_s[pixl] = 1.f / (1.f + expf(-alin));
    }
    __syncthreads();

    int tx = tid & 15, ty = tid >> 4;
    int oc0 = ty * 8, px0 = tx * 8;
    float acc[8][8];
#pragma unroll
    for (int o = 0; o < 8; o++) {
        float cb = ceb_s[oc0 + o];
#pragma unroll
        for (int p = 0; p < 8; p++) acc[o][p] = cb;
    }
#pragma unroll 4
    for (int d = 0; d < D_; d++) {
        float4 a0 = *reinterpret_cast<const float4*>(&cep_s[d * 128 + oc0]);
        float4 a1 = *reinterpret_cast<const float4*>(&cep_s[d * 128 + oc0 + 4]);
        float4 b0 = *reinterpret_cast<const float4*>(&cn_s[d * 136 + px0]);
        float4 b1 = *reinterpret_cast<const float4*>(&cn_s[d * 136 + px0 + 4]);
        float av[8] = {a0.x, a0.y, a0.z, a0.w, a1.x, a1.y, a1.z, a1.w};
        float bv[8] = {b0.x, b0.y, b0.z, b0.w, b1.x, b1.y, b1.z, b1.w};
#pragma unroll
        for (int o = 0; o < 8; o++)
#pragma unroll
            for (int p = 0; p < 8; p++) acc[o][p] += av[o] * bv[p];
    }
    __syncthreads();

#pragma unroll
    for (int o = 0; o < 8; o++) {
        int oc = oc0 + o;
        const float* trow = t_feat + (size_t)b * C_ * HW_ + (size_t)oc * HW_ + pix0 + px0;
        float4 t0 = *reinterpret_cast<const float4*>(trow);
        float4 t1 = *reinterpret_cast<const float4*>(trow + 4);
        float tvv[8] = {t0.x, t0.y, t0.z, t0.w, t1.x, t1.y, t1.z, t1.w};
        float wv = ntw_s[oc], bb = ntb_s[oc];
        unsigned hq[4];
#pragma unroll
        for (int p = 0; p < 8; p++) {
            float tv = (tvv[p] - mu_t) * inv_t * wv + bb;
            float al = alp_s[px0 + p];
            float f = al * tv + (1.f - al) * acc[o][p];
            unsigned short us = __half_as_ushort(__float2half_rn(f));
            if ((p & 1) == 0) hq[p >> 1] = us;
            else hq[p >> 1] |= ((unsigned)us << 16);
        }
        *reinterpret_cast<uint4*>(&fu_s[oc * 136 + px0]) = make_uint4(hq[0], hq[1], hq[2], hq[3]);
    }
    __syncthreads();

#pragma unroll
    for (int j = 0; j < 8; j++) {
        int item = tid + j * 256;
        int oc8 = item >> 7;
        int pixl = item & 127;
        int pixg = pix0 + pixl;
        int h = pixg / W_, w = pixg % W_;
        unsigned hq[4];
#pragma unroll
        for (int o = 0; o < 8; o++) {
            unsigned short us = __half_as_ushort(fu_s[(oc8 * 8 + o) * 136 + pixl]);
            if ((o & 1) == 0) hq[o >> 1] = us;
            else hq[o >> 1] |= ((unsigned)us << 16);
        }
        uint4 val = make_uint4(hq[0], hq[1], hq[2], hq[3]);
        size_t pbase = ((size_t)(b * PH_ + h + 1) * PW_ + (w + 1)) * C_ + oc8 * 8;
        *reinterpret_cast<uint4*>(&g_phi[pbase]) = val;
        bool top = (h == 1), bot = (h == H_ - 2);
        bool lef = (w == 1), rig = (w == W_ - 2);
        if (top | bot | lef | rig) {
            const size_t ROW2 = 2 * (size_t)PW_ * C_;
            if (top) *reinterpret_cast<uint4*>(&g_phi[pbase - ROW2]) = val;
            if (bot) *reinterpret_cast<uint4*>(&g_phi[pbase + ROW2]) = val;
            if (lef) *reinterpret_cast<uint4*>(&g_phi[pbase - 2 * C_]) = val;
            if (rig) *reinterpret_cast<uint4*>(&g_phi[pbase + 2 * C_]) = val;
            if (top && lef) *reinterpret_cast<uint4*>(&g_phi[pbase - ROW2 - 2 * C_]) = val;
            if (top && rig) *reinterpret_cast<uint4*>(&g_phi[pbase - ROW2 + 2 * C_]) = val;
            if (bot && lef) *reinterpret_cast<uint4*>(&g_phi[pbase + ROW2 - 2 * C_]) = val;
            if (bot && rig) *reinterpret_cast<uint4*>(&g_phi[pbase + ROW2 + 2 * C_]) = val;
        }
    }
}

// ---------------- mma.sync implicit-GEMM conv (18 iters, K=64) ----------------
#define A_HI  0
#define B_OFF 23040
#define CONV_SMEM 55808

__global__ void __launch_bounds__(256, 2) k_conv_mma(const float* __restrict__ rc_b,
                                                     float* __restrict__ out) {
    extern __shared__ __align__(128) char smem[];
    uint32_t sb = smem_u32(smem);
    int tid = threadIdx.x, lane = tid & 31, wid = tid >> 5;
    int warp_m = wid & 3, warp_n = wid >> 2;

    int bx = blockIdx.x % 20;
    int by = (blockIdx.x / 20) % 12;
    int b  = blockIdx.x / 240;
    int h0 = by * 8, w0 = bx * 16;
    size_t pbase = ((size_t)(b * PH_ + h0) * PW_ + w0) * C_;

    int m_loc = lane & 15, khalf_a = lane >> 4;
    int rA[2], cA[2];
#pragma unroll
    for (int mt = 0; mt < 2; mt++) {
        int m_abs = warp_m * 32 + mt * 16 + m_loc;
        rA[mt] = m_abs >> 4;
        cA[mt] = m_abs & 15;
    }
    int subB = lane >> 3;
    int nl = (lane & 7) + ((subB & 2) << 2);
    int khalf_b = subB & 1;
    uint32_t bRow[4]; int bSw[4];
#pragma unroll
    for (int nb4 = 0; nb4 < 4; nb4++) {
        int oc = warp_n * 64 + nb4 * 16 + nl;
        bRow[nb4] = (uint32_t)oc * 128;
        bSw[nb4]  = oc & 7;
    }

    float acc[2][8][4];
#pragma unroll
    for (int mt = 0; mt < 2; mt++)
#pragma unroll
        for (int n = 0; n < 8; n++)
#pragma unroll
            for (int e = 0; e < 4; e++) acc[mt][n][e] = 0.f;

    {
        const uint4* s0 = reinterpret_cast<const uint4*>(g_wH[0]);
#pragma unroll
        for (int j = 0; j < 4; j++) {
            int idx = tid + j * 256;
            CP16(sb + B_OFF + idx * 16, s0 + idx);
        }
        CP_COMMIT();
    }

    for (int it = 0; it < 18; it++) {
        int chunk = it / 9, tap = it % 9, buf = it & 1;
        int dy = tap / 3, dx = tap % 3;
        __syncthreads();

        if (tap == 0) {
            for (int i = tid; i < 1440; i += 256) {
                int row = i >> 3, ch = i & 7;
                int pr = row / 18, pc = row % 18;
                size_t g = pbase + ((size_t)pr * PW_ + pc) * C_ + chunk * 64 + ch * 8;
                uint32_t so = (uint32_t)row * 128 + ((ch ^ (row & 7)) << 4);
                CP16(sb + A_HI + so, &g_phi[g]);
            }
            CP_COMMIT();
        }
        if (it + 1 < 18) {
            const uint4* s0 = reinterpret_cast<const uint4*>(g_wH[it + 1]);
            uint32_t d0 = sb + B_OFF + (buf ^ 1) * 16384;
#pragma unroll
            for (int j = 0; j < 4; j++) {
                int idx = tid + j * 256;
                CP16(d0 + idx * 16, s0 + idx);
            }
        }
        CP_COMMIT();
        CP_WAIT(1);
        __syncthreads();

        uint32_t bbase = sb + B_OFF + buf * 16384;
        int rowA[2], swA[2];
#pragma unroll
        for (int mt = 0; mt < 2; mt++) {
            rowA[mt] = (rA[mt] + dy) * 18 + cA[mt] + dx;
            swA[mt]  = rowA[mt] & 7;
        }

#pragma unroll
        for (int k16 = 0; k16 < 4; k16++) {
            int chA = k16 * 2 + khalf_a;
            int chB = k16 * 2 + khalf_b;
            uint32_t ah[2][4];
#pragma unroll
            for (int mt = 0; mt < 2; mt++) {
                uint32_t off = (uint32_t)rowA[mt] * 128 + ((chA ^ swA[mt]) << 4);
                ldsm_x4(ah[mt], sb + A_HI + off);
            }
            uint32_t bh[4][4];
#pragma unroll
            for (int nb4 = 0; nb4 < 4; nb4++) {
                uint32_t off = bRow[nb4] + ((chB ^ bSw[nb4]) << 4);
                ldsm_x4(bh[nb4], bbase + off);
            }
#pragma unroll
            for (int mt = 0; mt < 2; mt++) {
#pragma unroll
                for (int nb4 = 0; nb4 < 4; nb4++) {
#pragma unroll
                    for (int half = 0; half < 2; half++) {
                        int n = nb4 * 2 + half;
                        mma16816h(acc[mt][n], ah[mt], bh[nb4][half * 2], bh[nb4][half * 2 + 1]);
                    }
                }
            }
        }
    }

    float* sf = reinterpret_cast<float*>(smem);
    int rbase = lane >> 2, cpair = (lane & 3) * 2;
#pragma unroll
    for (int p = 0; p < 2; p++) {
        __syncthreads();
        if (warp_n == p) {
#pragma unroll
            for (int mt = 0; mt < 2; mt++)
#pragma unroll
                for (int nbl = 0; nbl < 8; nbl++)
#pragma unroll
                    for (int e = 0; e < 4; e++) {
                        int m   = warp_m * 32 + mt * 16 + rbase + ((e >> 1) << 3);
                        int ocl = nbl * 8 + cpair + (e & 1);
                        sf[ocl * 132 + m] = acc[mt][nbl][e];
                    }
        }
        __syncthreads();
#pragma unroll
        for (int j = 0; j < 8; j++) {
            int idx = tid + j * 256;
            int ocl = idx >> 5, q = idx & 31;
            int r = q >> 2, cc = (q & 3) * 4;
            float4 v = *reinterpret_cast<const float4*>(&sf[ocl * 132 + r * 16 + cc]);
            int oc = p * 64 + ocl;
            float bias = rc_b[oc];
            v.x += bias; v.y += bias; v.z += bias; v.w += bias;
            *reinterpret_cast<float4*>(&out[(size_t)(b * C_ + oc) * HW_ + (h0 + r) * W_ + w0 + cc]) = v;
            float s = (v.x + v.y) + (v.z + v.w);
#pragma unroll
            for (int o = 16; o > 0; o >>= 1) s += __shfl_xor_sync(0xFFFFFFFFu, s, o);
            if (lane == 0) g_cpart[(size_t)blockIdx.x * 128 + oc] = s;
        }
    }
}

// ---------------- squeeze-excite ----------------
__global__ void __launch_bounds__(1024) k_se2(const float* __restrict__ se_w1,
                                              const float* __restrict__ se_w2) {
    __shared__ float part[4][256];
    __shared__ float mean_s[256];
    __shared__ float y1s[16];
    int tid = threadIdx.x;
    int q = tid >> 8, bc = tid & 255;
    int b = bc >> 7, c = bc & 127;
    float s = 0.f;
    for (int t = q * 60; t < q * 60 + 60; t++)
        s += g_cpart[(size_t)(b * 240 + t) * 128 + c];
    part[q][bc] = s;
    __syncthreads();
    if (tid < 256) {
        float m = part[0][tid] + part[1][tid] + part[2][tid] + part[3][tid];
        mean_s[tid] = m / (float)HW_;
    }
    __syncthreads();
    if (tid < 16) {
        int bb = tid / 8, j = tid % 8;
        float s2 = 0.f;
        for (int cc = 0; cc < C_; cc++) s2 += mean_s[bb * 128 + cc] * se_w1[j * C_ + cc];
        y1s[tid] = fmaxf(s2, 0.f);
    }
    __syncthreads();
    if (tid < 256) {
        int bb = tid >> 7, cc = tid & 127;
        float s3 = 0.f;
#pragma unroll
        for (int j = 0; j < 8; j++) s3 += y1s[bb * 8 + j] * se_w2[cc * 8 + j];
        g_yscale[tid] = 1.f / (1.f + expf(-s3));
    }
}

__global__ void __launch_bounds__(256) k_elu(float* __restrict__ out) {
    int idx4 = blockIdx.x * 256 + threadIdx.x;
    float ysc = g_yscale[(idx4 * 4) / HW_];
    float4 v = reinterpret_cast<float4*>(out)[idx4];
    v.x *= ysc; v.y *= ysc; v.z *= ysc; v.w *= ysc;
    v.x = v.x > 0.f ? v.x : expm1f(v.x);
    v.y = v.y > 0.f ? v.y : expm1f(v.y);
    v.z = v.z > 0.f ? v.z : expm1f(v.z);
    v.w = v.w > 0.f ? v.w : expm1f(v.w);
    reinterpret_cast<float4*>(out)[idx4] = v;
}

// ---------------- launch ----------------
extern "C" void kernel_launch(void* const* d_in, const int* in_sizes, int n_in,
                              void* d_out, int out_size) {
    const float* t_feat  = (const float*)d_in[0];
    const float* s_feat  = (const float*)d_in[1];
    const float* directs = (const float*)d_in[2];
    const float* disp    = (const float*)d_in[3];
    const float* q_w     = (const float*)d_in[4];
    const float* q_b     = (const float*)d_in[5];
    const float* k_w     = (const float*)d_in[6];
    const float* k_b     = (const float*)d_in[7];
    const float* cf_w    = (const float*)d_in[8];
    const float* nt_w    = (const float*)d_in[10];
    const float* nt_b    = (const float*)d_in[11];
    const float* nc_w    = (const float*)d_in[12];
    const float* nc_b    = (const float*)d_in[13];
    const float* ce_w    = (const float*)d_in[14];
    const float* ce_b    = (const float*)d_in[15];
    const float* fa_w    = (const float*)d_in[16];
    const float* fa_b    = (const float*)d_in[17];
    const float* rc_w    = (const float*)d_in[18];
    const float* rc_b    = (const float*)d_in[19];
    const float* se_w1   = (const float*)d_in[20];
    const float* se_w2   = (const float*)d_in[21];
    float* out = (float*)d_out;

    cudaFuncSetAttribute(k_conv_mma, cudaFuncAttributeMaxDynamicSharedMemorySize, CONV_SMEM);
    cudaFuncSetAttribute(k_simqk, cudaFuncAttributeMaxDynamicSharedMemorySize, SIMQK_SMEM);
    cudaFuncSetAttribute(k_fuse, cudaFuncAttributeMaxDynamicSharedMemorySize, FUSE_SMEM);

    k_prepall<<<19, 256>>>(fa_w, ce_w, ce_b, nt_w, nt_b, rc_w);
    k_simqk<<<dim3(H_, B_), 2 * W_, SIMQK_SMEM>>>(t_feat, s_feat, q_w, q_b, k_w, k_b, disp, directs);
    k_costsoft<<<dim3(H_ * 5, B_), dim3(64, 2)>>>(cf_w, out);
    k_statsfinal<<<4, 512>>>();
    k_fuse<<<480, 256, FUSE_SMEM>>>(out, t_feat, nt_w, nt_b, nc_w, nc_b, ce_w, ce_b, fa_b);
    k_conv_mma<<<480, 256, CONV_SMEM>>>(rc_b, out);
    k_se2<<<1, 1024>>>(se_w1, se_w2);
    k_elu<<<XEL_ / 1024, 256>>>(out);
}

// round 17
// speedup vs baseline: 1.1503x; 1.1503x over previous
#include <cuda_runtime.h>
#include <cuda_fp16.h>
#include <math.h>
#include <stdint.h>

#define B_   2
#define C_   128
#define H_   96
#define W_   320
#define HW_  30720
#define CQ_  32
#define D_   32
#define NPIX_ (B_*HW_)
#define XEL_  (B_*C_*HW_)
#define NCEL_ (B_*D_*HW_)
#define PH_  98
#define PW_  322

typedef unsigned long long u64;

#define FMA2(d,a,b,c) asm("fma.rn.f32x2 %0, %1, %2, %3;" : "=l"(d) : "l"(a), "l"(b), "l"(c))
#define PACK2(d,lo,hi) asm("mov.b64 %0, {%1, %2};" : "=l"(d) : "r"(__float_as_uint(lo)), "r"(__float_as_uint(hi)))
#define UNPK2(lo,hi,s) do { unsigned _a,_b; asm("mov.b64 {%0, %1}, %2;" : "=r"(_a), "=r"(_b) : "l"(s)); lo=__uint_as_float(_a); hi=__uint_as_float(_b); } while(0)

// ---------------- scratch ----------------
__device__ float  g_sim[NCEL_];
__device__ __align__(16) __half g_phi[(size_t)B_*PH_*PW_*C_];
__device__ __align__(16) unsigned short g_wH[18][8192];
__device__ float  g_faproj[40];
__device__ float  g_fw[C_];
__device__ float  g_partf[4*480*2];
__device__ float  g_stats[8];
__device__ float  g_cpart[480*128];
__device__ float  g_yscale[B_*C_];

// ---------------- low-level helpers ----------------
__device__ __forceinline__ uint32_t smem_u32(const void* p) {
    uint32_t a;
    asm("{ .reg .u64 t; cvta.to.shared.u64 t, %1; cvt.u32.u64 %0, t; }" : "=r"(a) : "l"(p));
    return a;
}
#define CP16(sm, gp) asm volatile("cp.async.cg.shared.global [%0], [%1], 16;" :: "r"(sm), "l"(gp) : "memory")
#define CP_COMMIT()  asm volatile("cp.async.commit_group;" ::: "memory")
#define CP_WAIT(n)   asm volatile("cp.async.wait_group %0;" :: "n"(n) : "memory")

__device__ __forceinline__ void ldsm_x4(uint32_t* r, uint32_t addr) {
    asm volatile("ldmatrix.sync.aligned.m8n8.x4.shared.b16 {%0,%1,%2,%3}, [%4];"
        : "=r"(r[0]), "=r"(r[1]), "=r"(r[2]), "=r"(r[3]) : "r"(addr));
}
__device__ __forceinline__ void mma16816h(float* d, const uint32_t* a, uint32_t b0, uint32_t b1) {
    asm volatile("mma.sync.aligned.m16n8k16.row.col.f32.f16.f16.f32 "
        "{%0,%1,%2,%3}, {%4,%5,%6,%7}, {%8,%9}, {%0,%1,%2,%3};"
        : "+f"(d[0]), "+f"(d[1]), "+f"(d[2]), "+f"(d[3])
        : "r"(a[0]), "r"(a[1]), "r"(a[2]), "r"(a[3]), "r"(b0), "r"(b1));
}

// ---------------- combined weight preprocessing ----------------
__global__ void __launch_bounds__(256) k_prepall(const float* __restrict__ fa_w,
                                                 const float* __restrict__ ce_w,
                                                 const float* __restrict__ ce_b,
                                                 const float* __restrict__ nt_w,
                                                 const float* __restrict__ nt_b,
                                                 const float* __restrict__ rc_w) {
    int blk = blockIdx.x;
    if (blk == 0) {
        int t = threadIdx.x;
        if (t < 32) {
            float s = 0.f;
            for (int o = 0; o < C_; o++) s += fa_w[C_ + o] * ce_w[o * D_ + t];
            g_faproj[t] = s;
        } else if (t == 32) {
            float s = 0.f;
            for (int o = 0; o < C_; o++) s += fa_w[C_ + o] * ce_b[o];
            g_faproj[32] = s;
        } else if (t == 33) {
            float s = 0.f;
            for (int c = 0; c < C_; c++) s += fa_w[c] * nt_b[c];
            g_faproj[33] = s;
        } else if (t == 34) {
            float s = 0.f;
            for (int c = 0; c < C_; c++) s += fa_w[c] * nt_w[c];
            g_faproj[34] = s;
        } else if (t >= 64 && t < 64 + C_) {
            int c = t - 64;
            g_fw[c] = fa_w[c] * nt_w[c];
        }
    } else {
        int it = blk - 1;
        int tap = it % 9, chunk = it / 9;
        for (int idx = threadIdx.x; idx < 8192; idx += 256) {
            int oc = idx >> 6, icl = idx & 63;
            int ic = chunk * 64 + icl;
            float w = rc_w[(oc * C_ + ic) * 9 + tap];
            int pos = oc * 64 + (((icl >> 3) ^ (oc & 7)) << 3) + (icl & 7);
            g_wH[it][pos] = __half_as_ushort(__float2half_rn(w));
        }
    }
}

// ---------------- fused q/k projection + warp + cosine sim + t-stats ----------------
// ksh TRANSPOSED: [w][36] floats (144B rows, 16B-aligned) -> sim loop uses LDS.128
#define SQ_KSH 0                         // 320*36*4 = 46080
#define SQ_WQ  46080                     // u64[128][16] 16384
#define SQ_WK  62464                     // 16384
#define SQ_BQ  78848
#define SQ_BK  78976
#define SQ_R1  79104
#define SQ_R2  79152
#define SIMQK_SMEM 79232

__global__ void __launch_bounds__(W_) k_simqk(const float* __restrict__ t_feat,
                                              const float* __restrict__ s_feat,
                                              const float* __restrict__ q_w,
                                              const float* __restrict__ q_b,
                                              const float* __restrict__ k_w,
                                              const float* __restrict__ k_b,
                                              const float* __restrict__ disp,
                                              const float* __restrict__ directs) {
    extern __shared__ __align__(16) char sm[];
    float* ksh = reinterpret_cast<float*>(sm + SQ_KSH);    // [w][36]
    u64*   wq  = reinterpret_cast<u64*>(sm + SQ_WQ);
    u64*   wk  = reinterpret_cast<u64*>(sm + SQ_WK);
    float* bq  = reinterpret_cast<float*>(sm + SQ_BQ);
    float* bk  = reinterpret_cast<float*>(sm + SQ_BK);
    float* r1  = reinterpret_cast<float*>(sm + SQ_R1);
    float* r2  = reinterpret_cast<float*>(sm + SQ_R2);

    int h = blockIdx.x, b = blockIdx.y;
    int w = threadIdx.x, lane = w & 31, wrp = w >> 5;

    for (int i = threadIdx.x; i < C_ * 16; i += W_) {
        int c = i >> 4, op = i & 15;
        u64 t;
        PACK2(t, q_w[(2 * op) * C_ + c], q_w[(2 * op + 1) * C_ + c]);
        wq[i] = t;
        PACK2(t, k_w[(2 * op) * C_ + c], k_w[(2 * op + 1) * C_ + c]);
        wk[i] = t;
    }
    if (threadIdx.x < CQ_) { bq[threadIdx.x] = q_b[threadIdx.x]; bk[threadIdx.x] = k_b[threadIdx.x]; }
    __syncthreads();

    // ---- k projection (writes own row of ksh as 8 STS.128) ----
    {
        const float* fp = s_feat + (size_t)b * C_ * HW_ + h * W_ + w;
        u64 acc[16];
#pragma unroll
        for (int o = 0; o < 16; o++) acc[o] = 0ULL;
#pragma unroll 4
        for (int c = 0; c < C_; c++) {
            float v = fp[(size_t)c * HW_];
            u64 v2; PACK2(v2, v, v);
#pragma unroll
            for (int op = 0; op < 16; op++) FMA2(acc[op], wk[c * 16 + op], v2, acc[op]);
        }
        float* krow = &ksh[w * 36];
#pragma unroll
        for (int g4 = 0; g4 < 8; g4++) {
            float l0, h0, l1, h1;
            UNPK2(l0, h0, acc[2 * g4]);
            UNPK2(l1, h1, acc[2 * g4 + 1]);
            float4 v = make_float4(l0 + bk[4 * g4], h0 + bk[4 * g4 + 1],
                                   l1 + bk[4 * g4 + 2], h1 + bk[4 * g4 + 3]);
            *reinterpret_cast<float4*>(&krow[g4 * 4]) = v;
        }
    }

    // ---- q projection + t_feat stats ----
    float qv[CQ_];
    float s1 = 0.f, s2 = 0.f;
    {
        const float* tp = t_feat + (size_t)b * C_ * HW_ + h * W_ + w;
        u64 acc[16];
#pragma unroll
        for (int o = 0; o < 16; o++) acc[o] = 0ULL;
#pragma unroll 4
        for (int c = 0; c < C_; c++) {
            float v = tp[(size_t)c * HW_];
            s1 += v; s2 += v * v;
            u64 v2; PACK2(v2, v, v);
#pragma unroll
            for (int op = 0; op < 16; op++) FMA2(acc[op], wq[c * 16 + op], v2, acc[op]);
        }
        float n2 = 0.f;
#pragma unroll
        for (int op = 0; op < 16; op++) {
            float lo, hi; UNPK2(lo, hi, acc[op]);
            lo += bq[2 * op]; hi += bq[2 * op + 1];
            qv[2 * op] = lo; qv[2 * op + 1] = hi;
            n2 += lo * lo + hi * hi;
        }
        float inv = 1.f / fmaxf(sqrtf(n2), 1e-12f);
#pragma unroll
        for (int c = 0; c < CQ_; c++) qv[c] *= inv;
    }
    __syncthreads();   // ksh complete

    // ---- warp + cosine sim: k rows via LDS.128 ----
    float dir = directs[b];
    float* sp = g_sim + (size_t)b * D_ * HW_ + h * W_ + w;
    for (int d = 0; d < D_; d++) {
        float pos = (float)w + disp[d] * dir * (float)(W_ - 1);
        pos = fminf(fmaxf(pos, 0.f), (float)(W_ - 1));
        int x0 = (int)floorf(pos);
        x0 = min(max(x0, 0), W_ - 1);
        int x1 = min(x0 + 1, W_ - 1);
        float t = pos - (float)x0;
        const float* k0 = &ksh[x0 * 36];
        const float* k1 = &ksh[x1 * 36];
        float dot = 0.f, kn2 = 0.f;
#pragma unroll
        for (int g4 = 0; g4 < 8; g4++) {
            float4 a = *reinterpret_cast<const float4*>(&k0[g4 * 4]);
            float4 c = *reinterpret_cast<const float4*>(&k1[g4 * 4]);
            float g0 = a.x + t * (c.x - a.x);
            float g1 = a.y + t * (c.y - a.y);
            float g2 = a.z + t * (c.z - a.z);
            float g3 = a.w + t * (c.w - a.w);
            dot += qv[g4 * 4 + 0] * g0 + qv[g4 * 4 + 1] * g1
                 + qv[g4 * 4 + 2] * g2 + qv[g4 * 4 + 3] * g3;
            kn2 += g0 * g0 + g1 * g1 + g2 * g2 + g3 * g3;
        }
        sp[(size_t)d * HW_] = dot / fmaxf(sqrtf(kn2), 1e-12f);
    }

    // ---- t-stats block reduce ----
#pragma unroll
    for (int o = 16; o > 0; o >>= 1) {
        s1 += __shfl_xor_sync(0xFFFFFFFFu, s1, o);
        s2 += __shfl_xor_sync(0xFFFFFFFFu, s2, o);
    }
    if (lane == 0) { r1[wrp] = s1; r2[wrp] = s2; }
    __syncthreads();
    if (threadIdx.x == 0) {
        float t1 = 0.f, t2 = 0.f;
#pragma unroll
        for (int i = 0; i < 10; i++) { t1 += r1[i]; t2 += r2[i]; }
        g_partf[((0 * 2 + b) * 480 + h) * 2 + 0] = t1;
        g_partf[((0 * 2 + b) * 480 + h) * 2 + 1] = t2;
    }
}

// ---------------- fused cost filter + softmax + c-stats ----------------
template<int Y>
__device__ __forceinline__ void cost_half(float* cl, const float* __restrict__ base,
                                          const float* __restrict__ wsh,
                                          int h, int w, int lane) {
#pragma unroll
    for (int j = 0; j < 17; j++) {
        const int dd = Y ? (15 + j) : j;
        const int t  = Y ? (j - 1) : j;
        float s0 = 0.f, s1 = 0.f, s2 = 0.f;
#pragma unroll
        for (int r = 0; r < 3; r++) {
            int hh = h + r - 1;
            bool ok = (hh >= 0) && (hh < H_);
            const float* row = base + ((size_t)dd * H_ + hh) * W_;
            float v = ok ? row[w] : 0.f;
            float vm = __shfl_up_sync(0xFFFFFFFFu, v, 1);
            float vp = __shfl_down_sync(0xFFFFFFFFu, v, 1);
            if (lane == 0)  vm = (ok && w > 0)      ? row[w - 1] : 0.f;
            if (lane == 31) vp = (ok && w < W_ - 1) ? row[w + 1] : 0.f;
            s0 += wsh[r * 3 + 0] * vm + wsh[r * 3 + 1] * v + wsh[r * 3 + 2] * vp;
            s1 += wsh[9 + r * 3 + 0] * vm + wsh[9 + r * 3 + 1] * v + wsh[9 + r * 3 + 2] * vp;
            s2 += wsh[18 + r * 3 + 0] * vm + wsh[18 + r * 3 + 1] * v + wsh[18 + r * 3 + 2] * vp;
        }
        if (t + 1 >= 0 && t + 1 < 16 && dd + 1 < D_) cl[t + 1] += s0;
        if (t >= 0 && t < 16)                        cl[t]     += s1;
        if (t - 1 >= 0 && t - 1 < 16)                cl[t - 1] += s2;
    }
}

__global__ void __launch_bounds__(128) k_costsoft(const float* __restrict__ cf_w,
                                                  float* __restrict__ out) {
    __shared__ float wsh[27];
    __shared__ float mx[2][64], sms[2][64];
    __shared__ float r1s[4], r2s[4];
    int h = blockIdx.x / 5, tile = blockIdx.x % 5, b = blockIdx.y;
    int wl = threadIdx.x, y = threadIdx.y;
    int w = tile * 64 + wl;
    int tid = y * 64 + wl;
    int lane = wl & 31;
    if (tid < 27) wsh[tid] = cf_w[tid];
    __syncthreads();

    const float* base = g_sim + (size_t)b * D_ * HW_;
    float cl[16];
#pragma unroll
    for (int j = 0; j < 16; j++) cl[j] = 0.f;
    if (y == 0) cost_half<0>(cl, base, wsh, h, w, lane);
    else        cost_half<1>(cl, base, wsh, h, w, lane);

    float m = -1e30f;
#pragma unroll
    for (int j = 0; j < 16; j++) m = fmaxf(m, cl[j]);
    mx[y][wl] = m;
    __syncthreads();
    m = fmaxf(mx[0][wl], mx[1][wl]);
    float sum = 0.f;
#pragma unroll
    for (int j = 0; j < 16; j++) { cl[j] = expf(cl[j] - m); sum += cl[j]; }
    sms[y][wl] = sum;
    __syncthreads();
    float invs = 1.f / (sms[0][wl] + sms[1][wl]);

    int d0 = y * 16;
    float* op = out + XEL_ + (size_t)b * D_ * HW_ + (size_t)d0 * HW_ + h * W_ + w;
    float ss1 = 0.f, ss2 = 0.f;
#pragma unroll
    for (int j = 0; j < 16; j++) {
        float v = cl[j] * invs;
        op[(size_t)j * HW_] = v;
        ss1 += v; ss2 += v * v;
    }
#pragma unroll
    for (int o = 16; o > 0; o >>= 1) {
        ss1 += __shfl_xor_sync(0xFFFFFFFFu, ss1, o);
        ss2 += __shfl_xor_sync(0xFFFFFFFFu, ss2, o);
    }
    if (lane == 0) { r1s[tid >> 5] = ss1; r2s[tid >> 5] = ss2; }
    __syncthreads();
    if (tid == 0) {
        g_partf[((1 * 2 + b) * 480 + h * 5 + tile) * 2 + 0] = r1s[0] + r1s[1] + r1s[2] + r1s[3];
        g_partf[((1 * 2 + b) * 480 + h * 5 + tile) * 2 + 1] = r2s[0] + r2s[1] + r2s[2] + r2s[3];
    }
}

// ---------------- stats finals ----------------
__global__ void __launch_bounds__(512) k_statsfinal() {
    __shared__ double sh1[512], sh2[512];
    int which = blockIdx.x >> 1, b = blockIdx.x & 1;
    int n = which ? 480 : 96;
    int t = threadIdx.x;
    double s1 = 0.0, s2 = 0.0;
    if (t < n) {
        s1 = (double)g_partf[((which * 2 + b) * 480 + t) * 2 + 0];
        s2 = (double)g_partf[((which * 2 + b) * 480 + t) * 2 + 1];
    }
    sh1[t] = s1; sh2[t] = s2;
    __syncthreads();
    for (int s = 256; s > 0; s >>= 1) {
        if (t < s) { sh1[t] += sh1[t + s]; sh2[t] += sh2[t + s]; }
        __syncthreads();
    }
    if (t == 0) {
        double N = which ? (double)(D_ * HW_) : (double)(C_ * HW_);
        double mu  = sh1[0] / N;
        double var = sh2[0] / N - mu * mu;
        g_stats[which * 4 + b * 2 + 0] = (float)mu;
        g_stats[which * 4 + b * 2 + 1] = (float)(1.0 / sqrt(var + 1e-5));
    }
}

// ---------------- fuse: GEMM-tiled cost-embed + gating ----------------
#define FS_CN    0
#define FS_CEP   17408
#define FS_FUSED 0
#define FS_ALPHA 34816
#define FS_NCW   35328
#define FS_NCB   35456
#define FS_PROJ  35584
#define FS_FW    35744
#define FS_NTW   36256
#define FS_NTB   36768
#define FS_CEB   37280
#define FUSE_SMEM 37888

__global__ void __launch_bounds__(256) k_fuse(const float* __restrict__ out_base,
                                              const float* __restrict__ t_feat,
                                              const float* __restrict__ nt_w,
                                              const float* __restrict__ nt_b,
                                              const float* __restrict__ nc_w,
                                              const float* __restrict__ nc_b,
                                              const float* __restrict__ ce_w,
                                              const float* __restrict__ ce_b,
                                              const float* __restrict__ fa_b) {
    extern __shared__ __align__(16) char sm[];
    float* cn_s   = reinterpret_cast<float*>(sm + FS_CN);
    float* cep_s  = reinterpret_cast<float*>(sm + FS_CEP);
    __half* fu_s  = reinterpret_cast<__half*>(sm + FS_FUSED);
    float* alp_s  = reinterpret_cast<float*>(sm + FS_ALPHA);
    float* ncw_s  = reinterpret_cast<float*>(sm + FS_NCW);
    float* ncb_s  = reinterpret_cast<float*>(sm + FS_NCB);
    float* proj_s = reinterpret_cast<float*>(sm + FS_PROJ);
    float* fw_s   = reinterpret_cast<float*>(sm + FS_FW);
    float* ntw_s  = reinterpret_cast<float*>(sm + FS_NTW);
    float* ntb_s  = reinterpret_cast<float*>(sm + FS_NTB);
    float* ceb_s  = reinterpret_cast<float*>(sm + FS_CEB);

    int tid = threadIdx.x;
    {
        const float4* cw4 = reinterpret_cast<const float4*>(ce_w);
#pragma unroll
        for (int j = 0; j < 4; j++) {
            int i4 = tid + j * 256;
            float4 v = cw4[i4];
            int base = i4 * 4;
            int oc = base >> 5, d = base & 31;
            cep_s[(d + 0) * 128 + oc] = v.x;
            cep_s[(d + 1) * 128 + oc] = v.y;
            cep_s[(d + 2) * 128 + oc] = v.z;
            cep_s[(d + 3) * 128 + oc] = v.w;
        }
    }
    if (tid < C_) {
        ntw_s[tid] = nt_w[tid];
        ntb_s[tid] = nt_b[tid];
        ceb_s[tid] = ce_b[tid];
        fw_s[tid]  = g_fw[tid];
    }
    if (tid < D_) { ncw_s[tid] = nc_w[tid]; ncb_s[tid] = nc_b[tid]; }
    if (tid >= 128 && tid < 168) proj_s[tid - 128] = g_faproj[tid - 128];
    __syncthreads();

    int blk = blockIdx.x;
    int b = (blk >= 240) ? 1 : 0;
    int pix0 = (blk * 128) % HW_;
    float mu_t = g_stats[b * 2 + 0], inv_t = g_stats[b * 2 + 1];
    float mu_c = g_stats[4 + b * 2 + 0], inv_c = g_stats[4 + b * 2 + 1];

    {
        int pixl = tid >> 1, half = tid & 1;
        int pixg = pix0 + pixl;
        const float* ncp = out_base + XEL_ + (size_t)b * D_ * HW_ + pixg;
        float alin = half ? 0.f
                          : (fa_b[0] + proj_s[32] + proj_s[33] - inv_t * mu_t * proj_s[34]);
#pragma unroll
        for (int j = 0; j < 16; j++) {
            int d = half * 16 + j;
            float v = (ncp[(size_t)d * HW_] - mu_c) * inv_c * ncw_s[d] + ncb_s[d];
            cn_s[d * 136 + pixl] = v;
            alin += proj_s[d] * v;
        }
        const float* tp = t_feat + (size_t)b * C_ * HW_ + pixg;
        float dotft = 0.f;
#pragma unroll 4
        for (int cc = 0; cc < 64; cc++) {
            int c = half * 64 + cc;
            dotft += fw_s[c] * tp[(size_t)c * HW_];
        }
        alin += inv_t * dotft;
        alin += __shfl_xor_sync(0xFFFFFFFFu, alin, 1);
        if (half == 0) alp_s[pixl] = 1.f / (1.f + expf(-alin));
    }
    __syncthreads();

    int tx = tid & 15, ty = tid >> 4;
    int oc0 = ty * 8, px0 = tx * 8;
    float acc[8][8];
#pragma unroll
    for (int o = 0; o < 8; o++) {
        float cb = ceb_s[oc0 + o];
#pragma unroll
        for (int p = 0; p < 8; p++) acc[o][p] = cb;
    }
#pragma unroll 4
    for (int d = 0; d < D_; d++) {
        float4 a0 = *reinterpret_cast<const float4*>(&cep_s[d * 128 + oc0]);
        float4 a1 = *reinterpret_cast<const float4*>(&cep_s[d * 128 + oc0 + 4]);
        float4 b0 = *reinterpret_cast<const float4*>(&cn_s[d * 136 + px0]);
        float4 b1 = *reinterpret_cast<const float4*>(&cn_s[d * 136 + px0 + 4]);
        float av[8] = {a0.x, a0.y, a0.z, a0.w, a1.x, a1.y, a1.z, a1.w};
        float bv[8] = {b0.x, b0.y, b0.z, b0.w, b1.x, b1.y, b1.z, b1.w};
#pragma unroll
        for (int o = 0; o < 8; o++)
#pragma unroll
            for (int p = 0; p < 8; p++) acc[o][p] += av[o] * bv[p];
    }
    __syncthreads();

#pragma unroll
    for (int o = 0; o < 8; o++) {
        int oc = oc0 + o;
        const float* trow = t_feat + (size_t)b * C_ * HW_ + (size_t)oc * HW_ + pix0 + px0;
        float4 t0 = *reinterpret_cast<const float4*>(trow);
        float4 t1 = *reinterpret_cast<const float4*>(trow + 4);
        float tvv[8] = {t0.x, t0.y, t0.z, t0.w, t1.x, t1.y, t1.z, t1.w};
        float wv = ntw_s[oc], bb = ntb_s[oc];
        unsigned hq[4];
#pragma unroll
        for (int p = 0; p < 8; p++) {
            float tv = (tvv[p] - mu_t) * inv_t * wv + bb;
            float al = alp_s[px0 + p];
            float f = al * tv + (1.f - al) * acc[o][p];
            unsigned short us = __half_as_ushort(__float2half_rn(f));
            if ((p & 1) == 0) hq[p >> 1] = us;
            else hq[p >> 1] |= ((unsigned)us << 16);
        }
        *reinterpret_cast<uint4*>(&fu_s[oc * 136 + px0]) = make_uint4(hq[0], hq[1], hq[2], hq[3]);
    }
    __syncthreads();

#pragma unroll
    for (int j = 0; j < 8; j++) {
        int item = tid + j * 256;
        int oc8 = item >> 7;
        int pixl = item & 127;
        int pixg = pix0 + pixl;
        int h = pixg / W_, w = pixg % W_;
        unsigned hq[4];
#pragma unroll
        for (int o = 0; o < 8; o++) {
            unsigned short us = __half_as_ushort(fu_s[(oc8 * 8 + o) * 136 + pixl]);
            if ((o & 1) == 0) hq[o >> 1] = us;
            else hq[o >> 1] |= ((unsigned)us << 16);
        }
        uint4 val = make_uint4(hq[0], hq[1], hq[2], hq[3]);
        size_t pbase = ((size_t)(b * PH_ + h + 1) * PW_ + (w + 1)) * C_ + oc8 * 8;
        *reinterpret_cast<uint4*>(&g_phi[pbase]) = val;
        bool top = (h == 1), bot = (h == H_ - 2);
        bool lef = (w == 1), rig = (w == W_ - 2);
        if (top | bot | lef | rig) {
            const size_t ROW2 = 2 * (size_t)PW_ * C_;
            if (top) *reinterpret_cast<uint4*>(&g_phi[pbase - ROW2]) = val;
            if (bot) *reinterpret_cast<uint4*>(&g_phi[pbase + ROW2]) = val;
            if (lef) *reinterpret_cast<uint4*>(&g_phi[pbase - 2 * C_]) = val;
            if (rig) *reinterpret_cast<uint4*>(&g_phi[pbase + 2 * C_]) = val;
            if (top && lef) *reinterpret_cast<uint4*>(&g_phi[pbase - ROW2 - 2 * C_]) = val;
            if (top && rig) *reinterpret_cast<uint4*>(&g_phi[pbase - ROW2 + 2 * C_]) = val;
            if (bot && lef) *reinterpret_cast<uint4*>(&g_phi[pbase + ROW2 - 2 * C_]) = val;
            if (bot && rig) *reinterpret_cast<uint4*>(&g_phi[pbase + ROW2 + 2 * C_]) = val;
        }
    }
}

// ---------------- mma.sync implicit-GEMM conv (18 iters, K=64) ----------------
#define A_HI  0
#define B_OFF 23040
#define CONV_SMEM 55808

__global__ void __launch_bounds__(256, 2) k_conv_mma(const float* __restrict__ rc_b,
                                                     float* __restrict__ out) {
    extern __shared__ __align__(128) char smem[];
    uint32_t sb = smem_u32(smem);
    int tid = threadIdx.x, lane = tid & 31, wid = tid >> 5;
    int warp_m = wid & 3, warp_n = wid >> 2;

    int bx = blockIdx.x % 20;
    int by = (blockIdx.x / 20) % 12;
    int b  = blockIdx.x / 240;
    int h0 = by * 8, w0 = bx * 16;
    size_t pbase = ((size_t)(b * PH_ + h0) * PW_ + w0) * C_;

    int m_loc = lane & 15, khalf_a = lane >> 4;
    int rA[2], cA[2];
#pragma unroll
    for (int mt = 0; mt < 2; mt++) {
        int m_abs = warp_m * 32 + mt * 16 + m_loc;
        rA[mt] = m_abs >> 4;
        cA[mt] = m_abs & 15;
    }
    int subB = lane >> 3;
    int nl = (lane & 7) + ((subB & 2) << 2);
    int khalf_b = subB & 1;
    uint32_t bRow[4]; int bSw[4];
#pragma unroll
    for (int nb4 = 0; nb4 < 4; nb4++) {
        int oc = warp_n * 64 + nb4 * 16 + nl;
        bRow[nb4] = (uint32_t)oc * 128;
        bSw[nb4]  = oc & 7;
    }

    float acc[2][8][4];
#pragma unroll
    for (int mt = 0; mt < 2; mt++)
#pragma unroll
        for (int n = 0; n < 8; n++)
#pragma unroll
            for (int e = 0; e < 4; e++) acc[mt][n][e] = 0.f;

    {
        const uint4* s0 = reinterpret_cast<const uint4*>(g_wH[0]);
#pragma unroll
        for (int j = 0; j < 4; j++) {
            int idx = tid + j * 256;
            CP16(sb + B_OFF + idx * 16, s0 + idx);
        }
        CP_COMMIT();
    }

    for (int it = 0; it < 18; it++) {
        int chunk = it / 9, tap = it % 9, buf = it & 1;
        int dy = tap / 3, dx = tap % 3;
        __syncthreads();

        if (tap == 0) {
            for (int i = tid; i < 1440; i += 256) {
                int row = i >> 3, ch = i & 7;
                int pr = row / 18, pc = row % 18;
                size_t g = pbase + ((size_t)pr * PW_ + pc) * C_ + chunk * 64 + ch * 8;
                uint32_t so = (uint32_t)row * 128 + ((ch ^ (row & 7)) << 4);
                CP16(sb + A_HI + so, &g_phi[g]);
            }
            CP_COMMIT();
        }
        if (it + 1 < 18) {
            const uint4* s0 = reinterpret_cast<const uint4*>(g_wH[it + 1]);
            uint32_t d0 = sb + B_OFF + (buf ^ 1) * 16384;
#pragma unroll
            for (int j = 0; j < 4; j++) {
                int idx = tid + j * 256;
                CP16(d0 + idx * 16, s0 + idx);
            }
        }
        CP_COMMIT();
        CP_WAIT(1);
        __syncthreads();

        uint32_t bbase = sb + B_OFF + buf * 16384;
        int rowA[2], swA[2];
#pragma unroll
        for (int mt = 0; mt < 2; mt++) {
            rowA[mt] = (rA[mt] + dy) * 18 + cA[mt] + dx;
            swA[mt]  = rowA[mt] & 7;
        }

#pragma unroll
        for (int k16 = 0; k16 < 4; k16++) {
            int chA = k16 * 2 + khalf_a;
            int chB = k16 * 2 + khalf_b;
            uint32_t ah[2][4];
#pragma unroll
            for (int mt = 0; mt < 2; mt++) {
                uint32_t off = (uint32_t)rowA[mt] * 128 + ((chA ^ swA[mt]) << 4);
                ldsm_x4(ah[mt], sb + A_HI + off);
            }
            uint32_t bh[4][4];
#pragma unroll
            for (int nb4 = 0; nb4 < 4; nb4++) {
                uint32_t off = bRow[nb4] + ((chB ^ bSw[nb4]) << 4);
                ldsm_x4(bh[nb4], bbase + off);
            }
#pragma unroll
            for (int mt = 0; mt < 2; mt++) {
#pragma unroll
                for (int nb4 = 0; nb4 < 4; nb4++) {
#pragma unroll
                    for (int half = 0; half < 2; half++) {
                        int n = nb4 * 2 + half;
                        mma16816h(acc[mt][n], ah[mt], bh[nb4][half * 2], bh[nb4][half * 2 + 1]);
                    }
                }
            }
        }
    }

    float* sf = reinterpret_cast<float*>(smem);
    int rbase = lane >> 2, cpair = (lane & 3) * 2;
#pragma unroll
    for (int p = 0; p < 2; p++) {
        __syncthreads();
        if (warp_n == p) {
#pragma unroll
            for (int mt = 0; mt < 2; mt++)
#pragma unroll
                for (int nbl = 0; nbl < 8; nbl++)
#pragma unroll
                    for (int e = 0; e < 4; e++) {
                        int m   = warp_m * 32 + mt * 16 + rbase + ((e >> 1) << 3);
                        int ocl = nbl * 8 + cpair + (e & 1);
                        sf[ocl * 132 + m] = acc[mt][nbl][e];
                    }
        }
        __syncthreads();
#pragma unroll
        for (int j = 0; j < 8; j++) {
            int idx = tid + j * 256;
            int ocl = idx >> 5, q = idx & 31;
            int r = q >> 2, cc = (q & 3) * 4;
            float4 v = *reinterpret_cast<const float4*>(&sf[ocl * 132 + r * 16 + cc]);
            int oc = p * 64 + ocl;
            float bias = rc_b[oc];
            v.x += bias; v.y += bias; v.z += bias; v.w += bias;
            *reinterpret_cast<float4*>(&out[(size_t)(b * C_ + oc) * HW_ + (h0 + r) * W_ + w0 + cc]) = v;
            float s = (v.x + v.y) + (v.z + v.w);
#pragma unroll
            for (int o = 16; o > 0; o >>= 1) s += __shfl_xor_sync(0xFFFFFFFFu, s, o);
            if (lane == 0) g_cpart[(size_t)blockIdx.x * 128 + oc] = s;
        }
    }
}

// ---------------- squeeze-excite ----------------
__global__ void __launch_bounds__(1024) k_se2(const float* __restrict__ se_w1,
                                              const float* __restrict__ se_w2) {
    __shared__ float part[4][256];
    __shared__ float mean_s[256];
    __shared__ float y1s[16];
    int tid = threadIdx.x;
    int q = tid >> 8, bc = tid & 255;
    int b = bc >> 7, c = bc & 127;
    float s = 0.f;
    for (int t = q * 60; t < q * 60 + 60; t++)
        s += g_cpart[(size_t)(b * 240 + t) * 128 + c];
    part[q][bc] = s;
    __syncthreads();
    if (tid < 256) {
        float m = part[0][tid] + part[1][tid] + part[2][tid] + part[3][tid];
        mean_s[tid] = m / (float)HW_;
    }
    __syncthreads();
    if (tid < 16) {
        int bb = tid / 8, j = tid % 8;
        float s2 = 0.f;
        for (int cc = 0; cc < C_; cc++) s2 += mean_s[bb * 128 + cc] * se_w1[j * C_ + cc];
        y1s[tid] = fmaxf(s2, 0.f);
    }
    __syncthreads();
    if (tid < 256) {
        int bb = tid >> 7, cc = tid & 127;
        float s3 = 0.f;
#pragma unroll
        for (int j = 0; j < 8; j++) s3 += y1s[bb * 8 + j] * se_w2[cc * 8 + j];
        g_yscale[tid] = 1.f / (1.f + expf(-s3));
    }
}

__global__ void __launch_bounds__(256) k_elu(float* __restrict__ out) {
    int idx4 = blockIdx.x * 256 + threadIdx.x;
    float ysc = g_yscale[(idx4 * 4) / HW_];
    float4 v = reinterpret_cast<float4*>(out)[idx4];
    v.x *= ysc; v.y *= ysc; v.z *= ysc; v.w *= ysc;
    v.x = v.x > 0.f ? v.x : expm1f(v.x);
    v.y = v.y > 0.f ? v.y : expm1f(v.y);
    v.z = v.z > 0.f ? v.z : expm1f(v.z);
    v.w = v.w > 0.f ? v.w : expm1f(v.w);
    reinterpret_cast<float4*>(out)[idx4] = v;
}

// ---------------- launch ----------------
extern "C" void kernel_launch(void* const* d_in, const int* in_sizes, int n_in,
                              void* d_out, int out_size) {
    const float* t_feat  = (const float*)d_in[0];
    const float* s_feat  = (const float*)d_in[1];
    const float* directs = (const float*)d_in[2];
    const float* disp    = (const float*)d_in[3];
    const float* q_w     = (const float*)d_in[4];
    const float* q_b     = (const float*)d_in[5];
    const float* k_w     = (const float*)d_in[6];
    const float* k_b     = (const float*)d_in[7];
    const float* cf_w    = (const float*)d_in[8];
    const float* nt_w    = (const float*)d_in[10];
    const float* nt_b    = (const float*)d_in[11];
    const float* nc_w    = (const float*)d_in[12];
    const float* nc_b    = (const float*)d_in[13];
    const float* ce_w    = (const float*)d_in[14];
    const float* ce_b    = (const float*)d_in[15];
    const float* fa_w    = (const float*)d_in[16];
    const float* fa_b    = (const float*)d_in[17];
    const float* rc_w    = (const float*)d_in[18];
    const float* rc_b    = (const float*)d_in[19];
    const float* se_w1   = (const float*)d_in[20];
    const float* se_w2   = (const float*)d_in[21];
    float* out = (float*)d_out;

    cudaFuncSetAttribute(k_conv_mma, cudaFuncAttributeMaxDynamicSharedMemorySize, CONV_SMEM);
    cudaFuncSetAttribute(k_simqk, cudaFuncAttributeMaxDynamicSharedMemorySize, SIMQK_SMEM);
    cudaFuncSetAttribute(k_fuse, cudaFuncAttributeMaxDynamicSharedMemorySize, FUSE_SMEM);

    k_prepall<<<19, 256>>>(fa_w, ce_w, ce_b, nt_w, nt_b, rc_w);
    k_simqk<<<dim3(H_, B_), W_, SIMQK_SMEM>>>(t_feat, s_feat, q_w, q_b, k_w, k_b, disp, directs);
    k_costsoft<<<dim3(H_ * 5, B_), dim3(64, 2)>>>(cf_w, out);
    k_statsfinal<<<4, 512>>>();
    k_fuse<<<480, 256, FUSE_SMEM>>>(out, t_feat, nt_w, nt_b, nc_w, nc_b, ce_w, ce_b, fa_b);
    k_conv_mma<<<480, 256, CONV_SMEM>>>(rc_b, out);
    k_se2<<<1, 1024>>>(se_w1, se_w2);
    k_elu<<<XEL_ / 1024, 256>>>(out);
}